// round 14
// baseline (speedup 1.0000x reference)
#include <cuda_runtime.h>
#include <cuda_fp16.h>
#include <math.h>
#include <stdint.h>

#define Hh 384
#define Ww 384
#define NC 10
#define HW (384*384)
#define BATCH 8
#define D64 64

typedef unsigned long long u64;

// ---- scratch (static device globals: allocation-free) ----
__device__ uint32_t g_h[(size_t)BATCH * D64 * (HW / 2)]; // 151 MB h as half2 pairs
__device__ float g_stats[128];                    // [b][g][{sum,sumsq}]
__device__ float g_mean[64];
__device__ float g_rstd[64];
__device__ u64   g_w2i[2048];                     // packed W2 pairs [d][pair]

// ---------------- packed f32x2 helpers ----------------
__device__ __forceinline__ u64 pack2(float x, float y) {
    u64 r;
    asm("mov.b64 %0, {%1, %2};" : "=l"(r) : "f"(x), "f"(y));
    return r;
}
__device__ __forceinline__ float2 unpk(u64 v) {
    float2 r;
    asm("mov.b64 {%0, %1}, %2;" : "=f"(r.x), "=f"(r.y) : "l"(v));
    return r;
}
__device__ __forceinline__ u64 fma2(u64 a, u64 b, u64 c) {
    u64 d;
    asm("fma.rn.f32x2 %0, %1, %2, %3;" : "=l"(d) : "l"(a), "l"(b), "l"(c));
    return d;
}
__device__ __forceinline__ u64 add2(u64 a, u64 b) {
    u64 d;
    asm("add.rn.f32x2 %0, %1, %2;" : "=l"(d) : "l"(a), "l"(b));
    return d;
}
__device__ __forceinline__ u64 mul2(u64 a, u64 b) {
    u64 d;
    asm("mul.rn.f32x2 %0, %1, %2;" : "=l"(d) : "l"(a), "l"(b));
    return d;
}
#define NEGM 0x8000000080000000ULL
__device__ __forceinline__ u64 sub2(u64 a, u64 b) { return add2(a, b ^ NEGM); }

// ---------------- K_init: zero stats + pack W2 pairs ----------------
__global__ void k_init(const float* __restrict__ W2) {
    int t = threadIdx.x;
    if (t < 128) g_stats[t] = 0.f;
    for (int i = t; i < 2048; i += 256) {
        int d = i >> 5, p = i & 31;
        g_w2i[d * 32 + p] = pack2(W2[(2 * p) * 64 + d], W2[(2 * p + 1) * 64 + d]);
    }
}

// ---------------- K1: softmax + neighbor features + W1 (f32x2) ----------
#define TLX 64
#define TLY 8
#define EX 68
#define EY 12
#define PAREA (EX * EY)          // 816

__global__ __launch_bounds__(256, 3) void k_feat(const float* __restrict__ x,
                                                 const float* __restrict__ W1,
                                                 const float* __restrict__ b1) {
    __shared__ float P[NC * PAREA];            // softmax probs, tile + 2px halo
    __shared__ __align__(16) u64 w1p[512];     // {w,w} duplicated
    __shared__ u64 b1p[64];
    __shared__ float sstat[16];

    const int b  = blockIdx.z;
    const int r0 = blockIdx.y * TLY, c0 = blockIdx.x * TLX;
    const int tid = threadIdx.x;

    for (int i = tid; i < 512; i += 256) { float w = W1[i]; w1p[i] = pack2(w, w); }
    if (tid < 64) { float bb = b1[tid]; b1p[tid] = pack2(bb, bb); }
    if (tid < 16) sstat[tid] = 0.f;

    // softmax over C for extended (halo) tile, replicate padding via clamp
    const float* xb = x + (size_t)b * NC * HW;
    for (int i = tid; i < PAREA; i += 256) {
        int er = i / EX, ec2 = i % EX;
        int gr = min(max(r0 + er - 2, 0), Hh - 1);
        int gc = min(max(c0 + ec2 - 2, 0), Ww - 1);
        const float* xp = xb + gr * Ww + gc;
        float v[NC];
        float m = -1e30f;
#pragma unroll
        for (int c = 0; c < NC; c++) { v[c] = xp[(size_t)c * HW]; m = fmaxf(m, v[c]); }
        float ssum = 0.f;
#pragma unroll
        for (int c = 0; c < NC; c++) { v[c] = __expf(v[c] - m); ssum += v[c]; }
        float inv = 1.f / ssum;
#pragma unroll
        for (int c = 0; c < NC; c++) P[c * PAREA + i] = v[c] * inv;
    }
    __syncthreads();

    const int txp = tid & 31;       // pixel-pair index (cols 2*txp, 2*txp+1)
    const int ty  = tid >> 5;       // tile row
    const int rowoff = ty * EX + 2 * txp;

    u64 macc3 = 0, macc5 = 0, pp = 0;
    u64 vacc3 = 0, vacc5 = 0, pbq3 = 0, pbq5 = 0;
    float maj3x = 0.f, maj3y = 0.f, maj5x = 0.f, maj5y = 0.f;
    float en3x = 0.f, en3y = 0.f, en5x = 0.f, en5y = 0.f;

    const u64 K9I  = pack2(1.f / 9.f,  1.f / 9.f);
    const u64 K25I = pack2(1.f / 25.f, 1.f / 25.f);

#pragma unroll 1
    for (int c = 0; c < NC; c++) {
        const float* base = P + c * PAREA + rowoff;
        u64 s5 = 0, q5 = 0, s3 = 0, q3 = 0, pcen = 0;
#pragma unroll
        for (int dr = 0; dr < 5; dr++) {
            const float* rp = base + dr * EX;
            float2 av = *(const float2*)rp;
            float2 bv = *(const float2*)(rp + 2);
            float2 cv = *(const float2*)(rp + 4);
            u64 p0 = pack2(av.x, av.y);
            u64 p1 = pack2(av.y, bv.x);
            u64 p2 = pack2(bv.x, bv.y);
            u64 p3 = pack2(bv.y, cv.x);
            u64 p4 = pack2(cv.x, cv.y);
            u64 s3r = add2(p1, add2(p2, p3));
            u64 s5r = add2(s3r, add2(p0, p4));
            u64 q3r = fma2(p3, p3, fma2(p2, p2, mul2(p1, p1)));
            u64 q5r = fma2(p4, p4, fma2(p0, p0, q3r));
            s5 = add2(s5, s5r);
            q5 = add2(q5, q5r);
            if (dr >= 1 && dr <= 3) {
                s3 = add2(s3, s3r);
                q3 = add2(q3, q3r);
            }
            if (dr == 2) pcen = p2;
        }
        macc3 = fma2(pcen, s3, macc3);
        macc5 = fma2(pcen, s5, macc5);
        pp    = fma2(pcen, pcen, pp);
        float2 s3f = unpk(s3), s5f = unpk(s5);
        maj3x = fmaxf(maj3x, s3f.x); maj3y = fmaxf(maj3y, s3f.y);
        maj5x = fmaxf(maj5x, s5f.x); maj5y = fmaxf(maj5y, s5f.y);
        u64 pb3 = mul2(s3, K9I), pb5 = mul2(s5, K25I);
        vacc3 = fma2(q3, K9I, vacc3);   pbq3 = fma2(pb3, pb3, pbq3);
        vacc5 = fma2(q5, K25I, vacc5);  pbq5 = fma2(pb5, pb5, pbq5);
        float2 pb3f = unpk(pb3), pb5f = unpk(pb5);
        float t0 = fmaxf(pb3f.x, 1e-8f); en3x = fmaf(t0, __logf(t0), en3x);
        float t1 = fmaxf(pb3f.y, 1e-8f); en3y = fmaf(t1, __logf(t1), en3y);
        float t2 = fmaxf(pb5f.x, 1e-8f); en5x = fmaf(t2, __logf(t2), en5x);
        float t3 = fmaxf(pb5f.y, 1e-8f); en5y = fmaf(t3, __logf(t3), en5y);
    }

    const float INV_LOGC = 0.434294481903252f; // 1/ln(10)
    u64 f2[8];
    f2[0] = mul2(sub2(macc3, pp), pack2(1.f / 8.f, 1.f / 8.f));
    f2[1] = mul2(pack2(maj3x, maj3y), K9I);
    f2[2] = pack2(fmaf(en3x, INV_LOGC, 1.f), fmaf(en3y, INV_LOGC, 1.f));
    f2[3] = sub2(vacc3, pbq3);
    f2[4] = mul2(sub2(macc5, pp), pack2(1.f / 24.f, 1.f / 24.f));
    f2[5] = mul2(pack2(maj5x, maj5y), K25I);
    f2[6] = pack2(fmaf(en5x, INV_LOGC, 1.f), fmaf(en5y, INV_LOGC, 1.f));
    f2[7] = sub2(vacc5, pbq5);

    // h = W1 f + b1 -> fp16 store ; stats group-by-group (small live set)
    const int pix = (r0 + ty) * Ww + c0 + 2 * txp;
    uint32_t* hb = g_h + (size_t)b * D64 * (HW / 2) + (pix >> 1);
#pragma unroll 1
    for (int g = 0; g < 8; g++) {
        u64 gs = 0, gq = 0;
#pragma unroll
        for (int j = 0; j < 8; j++) {
            int d = g * 8 + j;
            const ulonglong2* wr = (const ulonglong2*)&w1p[d * 8];
            ulonglong2 w01 = wr[0];
            ulonglong2 w23 = wr[1];
            ulonglong2 w45 = wr[2];
            ulonglong2 w67 = wr[3];
            u64 acc = b1p[d];
            acc = fma2(w01.x, f2[0], acc);
            acc = fma2(w01.y, f2[1], acc);
            acc = fma2(w23.x, f2[2], acc);
            acc = fma2(w23.y, f2[3], acc);
            acc = fma2(w45.x, f2[4], acc);
            acc = fma2(w45.y, f2[5], acc);
            acc = fma2(w67.x, f2[6], acc);
            acc = fma2(w67.y, f2[7], acc);
            float2 av = unpk(acc);
            __half2 hh = __floats2half2_rn(av.x, av.y);
            __stcs((__half2*)&hb[(size_t)d * (HW / 2)], hh);
            gs = add2(gs, acc);
            gq = fma2(acc, acc, gq);
        }
        float2 sa = unpk(gs), qa = unpk(gq);
        float a = sa.x + sa.y, q = qa.x + qa.y;
#pragma unroll
        for (int o = 16; o; o >>= 1) {
            a += __shfl_xor_sync(0xffffffffu, a, o);
            q += __shfl_xor_sync(0xffffffffu, q, o);
        }
        if (txp == 0) { atomicAdd(&sstat[2 * g], a); atomicAdd(&sstat[2 * g + 1], q); }
    }
    __syncthreads();
    if (tid < 16) atomicAdd(&g_stats[b * 16 + tid], sstat[tid]);
}

// ---------------- K2: finalize GN stats ----------------
__global__ void k_stats() {
    int i = threadIdx.x;
    if (i < 64) {
        const float invN = 1.f / (8.f * (float)HW);
        float s  = g_stats[2 * i];
        float ss = g_stats[2 * i + 1];
        float mean = s * invN;
        float var  = ss * invN - mean * mean;
        g_mean[i] = mean;
        g_rstd[i] = rsqrtf(var + 1e-5f);
    }
}

// -------- K3: GN + GELU + W2 (f32x2, fp16 G tile, 3 CTAs/SM) --------------
// branch-free erf-GELU (A&S 7.1.26, abs err ~1.5e-7)
__device__ __forceinline__ float gelu_fast(float h) {
    float z = h * 0.70710678118f;
    float x = fabsf(z);
    float t = __fdividef(1.f, fmaf(0.3275911f, x, 1.f));
    float p = fmaf(1.061405429f, t, -1.453152027f);
    p = fmaf(p, t, 1.421413741f);
    p = fmaf(p, t, -0.284496736f);
    p = fmaf(p, t, 0.254829592f);
    p = p * t;
    float e = __expf(-x * x);
    float er = fmaf(-p, e, 1.f);
    er = copysignf(er, z);
    return 0.5f * h * (1.f + er);
}

// smem: G16 [64][64] half2 = 16KB ; w2i [64][32] u64 = 16KB ; sp 768B
#define G_OFF  0
#define W_OFF  16384
#define SP_OFF 32768
#define SMEM3  (32768 + 768)

__global__ void __launch_bounds__(256, 3) k_out(const float* __restrict__ gnw,
                                                const float* __restrict__ gnb,
                                                const float* __restrict__ b2,
                                                float* __restrict__ out) {
    extern __shared__ char s[];
    uint32_t* G16 = (uint32_t*)(s + G_OFF);  // [d][pxpair] 64 x 64 half2
    u64* w2i  = (u64*)(s + W_OFF);           // [d][pair] 64 x 32
    float* sp = (float*)(s + SP_OFF);        // a[64], c[64], b2[64]

    const int b  = blockIdx.y;
    const int p0 = blockIdx.x * 128;
    const int t  = threadIdx.x;

    if (t < 64) {
        int g = t >> 3;
        float a = g_rstd[b * 8 + g] * gnw[t];
        sp[t]       = a;
        sp[64 + t]  = gnb[t] - g_mean[b * 8 + g] * a;
        sp[128 + t] = b2[t];
    }
    // copy prepacked W2 table (coalesced)
    for (int i = t; i < 1024; i += 256)
        *(ulonglong2*)&w2i[i * 2] = *(const ulonglong2*)&g_w2i[i * 2];

    // ---- GN + GELU into G16: thread = 4 px x 8 d (fp16 h loads before sync) ----
    const uint32_t* hbu = g_h + (size_t)b * D64 * (HW / 2) + (p0 >> 1);
    const int pxh = (t & 31) * 2;           // half2 index for this thread's 4 px
    const int dblk = t >> 5;                // 0..7
    uint2 hv2[8];
#pragma unroll
    for (int j = 0; j < 8; j++)
        hv2[j] = __ldcs((const uint2*)&hbu[(size_t)(dblk * 8 + j) * (HW / 2) + pxh]);
    __syncthreads();                        // sp + w2i visible
    {
#pragma unroll
        for (int j = 0; j < 8; j++) {
            int d = dblk * 8 + j;
            float a = sp[d], c = sp[64 + d];
            float2 f01 = __half22float2(*(__half2*)&hv2[j].x);
            float2 f23 = __half22float2(*(__half2*)&hv2[j].y);
            float r0 = gelu_fast(fmaf(f01.x, a, c));
            float r1 = gelu_fast(fmaf(f01.y, a, c));
            float r2 = gelu_fast(fmaf(f23.x, a, c));
            float r3 = gelu_fast(fmaf(f23.y, a, c));
            __half2 g01 = __floats2half2_rn(r0, r1);
            __half2 g23 = __floats2half2_rn(r2, r3);
            uint2 pkt;
            pkt.x = *(uint32_t*)&g01;
            pkt.y = *(uint32_t*)&g23;
            *(uint2*)&G16[d * 64 + pxh] = pkt;
        }
    }
    __syncthreads();

    // ---- GEMM: warp = 128 px x 8 d2 ; thread = 4 px x 4 d2-pairs ----
    const int lane = t & 31;
    const int wrp  = t >> 5;                    // 0..7 -> d2 base 8*wrp
    const int pxb  = lane * 4;
    u64 acc[4][4];                              // [pair][px]
#pragma unroll
    for (int p = 0; p < 4; p++) {
        u64 bp = pack2(sp[128 + 8 * wrp + 2 * p], sp[128 + 8 * wrp + 2 * p + 1]);
#pragma unroll
        for (int x2 = 0; x2 < 4; x2++) acc[p][x2] = bp;
    }

    const uint32_t* Gp = G16 + lane * 2;
    const u64*   wp = w2i + 4 * wrp;
#pragma unroll 4
    for (int d = 0; d < 64; d++) {
        uint2 gv = *(const uint2*)Gp;           // 4 px as 2 half2 (LDS.64)
        float2 f01 = __half22float2(*(__half2*)&gv.x);
        float2 f23 = __half22float2(*(__half2*)&gv.y);
        u64 g0 = pack2(f01.x, f01.x);
        u64 g1 = pack2(f01.y, f01.y);
        u64 g2 = pack2(f23.x, f23.x);
        u64 g3 = pack2(f23.y, f23.y);
        ulonglong2 wa = *(const ulonglong2*)(wp);       // pairs 0,1 (uniform)
        ulonglong2 wb = *(const ulonglong2*)(wp + 2);   // pairs 2,3 (uniform)
        acc[0][0] = fma2(wa.x, g0, acc[0][0]);
        acc[0][1] = fma2(wa.x, g1, acc[0][1]);
        acc[0][2] = fma2(wa.x, g2, acc[0][2]);
        acc[0][3] = fma2(wa.x, g3, acc[0][3]);
        acc[1][0] = fma2(wa.y, g0, acc[1][0]);
        acc[1][1] = fma2(wa.y, g1, acc[1][1]);
        acc[1][2] = fma2(wa.y, g2, acc[1][2]);
        acc[1][3] = fma2(wa.y, g3, acc[1][3]);
        acc[2][0] = fma2(wb.x, g0, acc[2][0]);
        acc[2][1] = fma2(wb.x, g1, acc[2][1]);
        acc[2][2] = fma2(wb.x, g2, acc[2][2]);
        acc[2][3] = fma2(wb.x, g3, acc[2][3]);
        acc[3][0] = fma2(wb.y, g0, acc[3][0]);
        acc[3][1] = fma2(wb.y, g1, acc[3][1]);
        acc[3][2] = fma2(wb.y, g2, acc[3][2]);
        acc[3][3] = fma2(wb.y, g3, acc[3][3]);
        Gp += 64; wp += 32;
    }

    // ---- stores: 8 coalesced STG.128 per thread (streaming) ----
    float* ob = out + (size_t)b * D64 * HW + p0 + pxb;
#pragma unroll
    for (int p = 0; p < 4; p++) {
        int d2 = 8 * wrp + 2 * p;
        float2 a0 = unpk(acc[p][0]);
        float2 a1 = unpk(acc[p][1]);
        float2 a2 = unpk(acc[p][2]);
        float2 a3 = unpk(acc[p][3]);
        float4 lo; lo.x = a0.x; lo.y = a1.x; lo.z = a2.x; lo.w = a3.x;
        float4 hi; hi.x = a0.y; hi.y = a1.y; hi.z = a2.y; hi.w = a3.y;
        __stcs((float4*)&ob[(size_t)d2 * HW], lo);
        __stcs((float4*)&ob[(size_t)(d2 + 1) * HW], hi);
    }
}

// ---------------- launch ----------------
extern "C" void kernel_launch(void* const* d_in, const int* in_sizes, int n_in,
                              void* d_out, int out_size) {
    const float* x   = (const float*)d_in[0];
    const float* W1  = (const float*)d_in[1];
    const float* b1  = (const float*)d_in[2];
    const float* gnw = (const float*)d_in[3];
    const float* gnb = (const float*)d_in[4];
    const float* W2  = (const float*)d_in[5];
    const float* b2  = (const float*)d_in[6];
    float* out = (float*)d_out;

    k_init<<<1, 256>>>(W2);

    dim3 g1(Ww / TLX, Hh / TLY, BATCH);   // 6 x 48 x 8
    k_feat<<<g1, 256>>>(x, W1, b1);

    k_stats<<<1, 64>>>();

    cudaFuncSetAttribute(k_out, cudaFuncAttributeMaxDynamicSharedMemorySize, SMEM3);
    dim3 g3(HW / 128, BATCH);             // 1152 x 8
    k_out<<<g3, 256, SMEM3>>>(gnw, gnb, b2, out);
}

// round 15
// speedup vs baseline: 1.1513x; 1.1513x over previous
#include <cuda_runtime.h>
#include <cuda_fp16.h>
#include <math.h>
#include <stdint.h>

#define Hh 384
#define Ww 384
#define NC 10
#define HW (384*384)
#define BATCH 8
#define D64 64

typedef unsigned long long u64;

// ---- scratch (static device globals: allocation-free) ----
__device__ uint32_t g_h[(size_t)BATCH * D64 * (HW / 2)]; // 151 MB h as half2 pairs
__device__ float g_stats[128];                    // [b][g][{sum,sumsq}]
__device__ u64   g_w2i[2048];                     // packed W2 pairs [d][pair]

// ---------------- packed f32x2 helpers ----------------
__device__ __forceinline__ u64 pack2(float x, float y) {
    u64 r;
    asm("mov.b64 %0, {%1, %2};" : "=l"(r) : "f"(x), "f"(y));
    return r;
}
__device__ __forceinline__ float2 unpk(u64 v) {
    float2 r;
    asm("mov.b64 {%0, %1}, %2;" : "=f"(r.x), "=f"(r.y) : "l"(v));
    return r;
}
__device__ __forceinline__ u64 fma2(u64 a, u64 b, u64 c) {
    u64 d;
    asm("fma.rn.f32x2 %0, %1, %2, %3;" : "=l"(d) : "l"(a), "l"(b), "l"(c));
    return d;
}
__device__ __forceinline__ u64 add2(u64 a, u64 b) {
    u64 d;
    asm("add.rn.f32x2 %0, %1, %2;" : "=l"(d) : "l"(a), "l"(b));
    return d;
}
__device__ __forceinline__ u64 mul2(u64 a, u64 b) {
    u64 d;
    asm("mul.rn.f32x2 %0, %1, %2;" : "=l"(d) : "l"(a), "l"(b));
    return d;
}
#define NEGM 0x8000000080000000ULL
__device__ __forceinline__ u64 sub2(u64 a, u64 b) { return add2(a, b ^ NEGM); }

// ---------------- K_init: zero stats + pack W2 pairs ----------------
__global__ void k_init(const float* __restrict__ W2) {
    int t = threadIdx.x;
    if (t < 128) g_stats[t] = 0.f;
    for (int i = t; i < 2048; i += 256) {
        int d = i >> 5, p = i & 31;
        g_w2i[d * 32 + p] = pack2(W2[(2 * p) * 64 + d], W2[(2 * p + 1) * 64 + d]);
    }
}

// ---------------- K1: softmax + neighbor features + W1 (f32x2) ----------
#define TLX 64
#define TLY 8
#define EX 68
#define EY 12
#define PAREA (EX * EY)          // 816

__global__ __launch_bounds__(256, 3) void k_feat(const float* __restrict__ x,
                                                 const float* __restrict__ W1,
                                                 const float* __restrict__ b1) {
    __shared__ float P[NC * PAREA];            // softmax probs, tile + 2px halo
    __shared__ __align__(16) u64 w1p[512];     // {w,w} duplicated
    __shared__ u64 b1p[64];
    __shared__ float sstat[16];

    const int b  = blockIdx.z;
    const int r0 = blockIdx.y * TLY, c0 = blockIdx.x * TLX;
    const int tid = threadIdx.x;

    for (int i = tid; i < 512; i += 256) { float w = W1[i]; w1p[i] = pack2(w, w); }
    if (tid < 64) { float bb = b1[tid]; b1p[tid] = pack2(bb, bb); }
    if (tid < 16) sstat[tid] = 0.f;

    // softmax over C for extended (halo) tile, replicate padding via clamp
    const float* xb = x + (size_t)b * NC * HW;
    for (int i = tid; i < PAREA; i += 256) {
        int er = i / EX, ec2 = i % EX;
        int gr = min(max(r0 + er - 2, 0), Hh - 1);
        int gc = min(max(c0 + ec2 - 2, 0), Ww - 1);
        const float* xp = xb + gr * Ww + gc;
        float v[NC];
        float m = -1e30f;
#pragma unroll
        for (int c = 0; c < NC; c++) { v[c] = xp[(size_t)c * HW]; m = fmaxf(m, v[c]); }
        float ssum = 0.f;
#pragma unroll
        for (int c = 0; c < NC; c++) { v[c] = __expf(v[c] - m); ssum += v[c]; }
        float inv = 1.f / ssum;
#pragma unroll
        for (int c = 0; c < NC; c++) P[c * PAREA + i] = v[c] * inv;
    }
    __syncthreads();

    const int txp = tid & 31;       // pixel-pair index (cols 2*txp, 2*txp+1)
    const int ty  = tid >> 5;       // tile row
    const int rowoff = ty * EX + 2 * txp;

    u64 macc3 = 0, macc5 = 0, pp = 0;
    u64 vacc3 = 0, vacc5 = 0, pbq3 = 0, pbq5 = 0;
    float maj3x = 0.f, maj3y = 0.f, maj5x = 0.f, maj5y = 0.f;
    float en3x = 0.f, en3y = 0.f, en5x = 0.f, en5y = 0.f;

    const u64 K9I  = pack2(1.f / 9.f,  1.f / 9.f);
    const u64 K25I = pack2(1.f / 25.f, 1.f / 25.f);

#pragma unroll 1
    for (int c = 0; c < NC; c++) {
        const float* base = P + c * PAREA + rowoff;
        u64 s5 = 0, q5 = 0, s3 = 0, q3 = 0, pcen = 0;
#pragma unroll
        for (int dr = 0; dr < 5; dr++) {
            const float* rp = base + dr * EX;
            float2 av = *(const float2*)rp;
            float2 bv = *(const float2*)(rp + 2);
            float2 cv = *(const float2*)(rp + 4);
            u64 p0 = pack2(av.x, av.y);
            u64 p1 = pack2(av.y, bv.x);
            u64 p2 = pack2(bv.x, bv.y);
            u64 p3 = pack2(bv.y, cv.x);
            u64 p4 = pack2(cv.x, cv.y);
            u64 s3r = add2(p1, add2(p2, p3));
            u64 s5r = add2(s3r, add2(p0, p4));
            u64 q3r = fma2(p3, p3, fma2(p2, p2, mul2(p1, p1)));
            u64 q5r = fma2(p4, p4, fma2(p0, p0, q3r));
            s5 = add2(s5, s5r);
            q5 = add2(q5, q5r);
            if (dr >= 1 && dr <= 3) {
                s3 = add2(s3, s3r);
                q3 = add2(q3, q3r);
            }
            if (dr == 2) pcen = p2;
        }
        macc3 = fma2(pcen, s3, macc3);
        macc5 = fma2(pcen, s5, macc5);
        pp    = fma2(pcen, pcen, pp);
        float2 s3f = unpk(s3), s5f = unpk(s5);
        maj3x = fmaxf(maj3x, s3f.x); maj3y = fmaxf(maj3y, s3f.y);
        maj5x = fmaxf(maj5x, s5f.x); maj5y = fmaxf(maj5y, s5f.y);
        u64 pb3 = mul2(s3, K9I), pb5 = mul2(s5, K25I);
        vacc3 = fma2(q3, K9I, vacc3);   pbq3 = fma2(pb3, pb3, pbq3);
        vacc5 = fma2(q5, K25I, vacc5);  pbq5 = fma2(pb5, pb5, pbq5);
        float2 pb3f = unpk(pb3), pb5f = unpk(pb5);
        float t0 = fmaxf(pb3f.x, 1e-8f); en3x = fmaf(t0, __logf(t0), en3x);
        float t1 = fmaxf(pb3f.y, 1e-8f); en3y = fmaf(t1, __logf(t1), en3y);
        float t2 = fmaxf(pb5f.x, 1e-8f); en5x = fmaf(t2, __logf(t2), en5x);
        float t3 = fmaxf(pb5f.y, 1e-8f); en5y = fmaf(t3, __logf(t3), en5y);
    }

    const float INV_LOGC = 0.434294481903252f; // 1/ln(10)
    u64 f2[8];
    f2[0] = mul2(sub2(macc3, pp), pack2(1.f / 8.f, 1.f / 8.f));
    f2[1] = mul2(pack2(maj3x, maj3y), K9I);
    f2[2] = pack2(fmaf(en3x, INV_LOGC, 1.f), fmaf(en3y, INV_LOGC, 1.f));
    f2[3] = sub2(vacc3, pbq3);
    f2[4] = mul2(sub2(macc5, pp), pack2(1.f / 24.f, 1.f / 24.f));
    f2[5] = mul2(pack2(maj5x, maj5y), K25I);
    f2[6] = pack2(fmaf(en5x, INV_LOGC, 1.f), fmaf(en5y, INV_LOGC, 1.f));
    f2[7] = sub2(vacc5, pbq5);

    // h = W1 f + b1 -> fp16 store ; stats group-by-group (small live set)
    const int pix = (r0 + ty) * Ww + c0 + 2 * txp;
    uint32_t* hb = g_h + (size_t)b * D64 * (HW / 2) + (pix >> 1);
#pragma unroll 1
    for (int g = 0; g < 8; g++) {
        u64 gs = 0, gq = 0;
#pragma unroll
        for (int j = 0; j < 8; j++) {
            int d = g * 8 + j;
            const ulonglong2* wr = (const ulonglong2*)&w1p[d * 8];
            ulonglong2 w01 = wr[0];
            ulonglong2 w23 = wr[1];
            ulonglong2 w45 = wr[2];
            ulonglong2 w67 = wr[3];
            u64 acc = b1p[d];
            acc = fma2(w01.x, f2[0], acc);
            acc = fma2(w01.y, f2[1], acc);
            acc = fma2(w23.x, f2[2], acc);
            acc = fma2(w23.y, f2[3], acc);
            acc = fma2(w45.x, f2[4], acc);
            acc = fma2(w45.y, f2[5], acc);
            acc = fma2(w67.x, f2[6], acc);
            acc = fma2(w67.y, f2[7], acc);
            float2 av = unpk(acc);
            __half2 hh = __floats2half2_rn(av.x, av.y);
            __stcs((__half2*)&hb[(size_t)d * (HW / 2)], hh);
            gs = add2(gs, acc);
            gq = fma2(acc, acc, gq);
        }
        float2 sa = unpk(gs), qa = unpk(gq);
        float a = sa.x + sa.y, q = qa.x + qa.y;
#pragma unroll
        for (int o = 16; o; o >>= 1) {
            a += __shfl_xor_sync(0xffffffffu, a, o);
            q += __shfl_xor_sync(0xffffffffu, q, o);
        }
        if (txp == 0) { atomicAdd(&sstat[2 * g], a); atomicAdd(&sstat[2 * g + 1], q); }
    }
    __syncthreads();
    if (tid < 16) atomicAdd(&g_stats[b * 16 + tid], sstat[tid]);
}

// -------- K3: GN + GELU + W2 (f32x2, X=128px/Y=4pairs per warp, 3 CTAs) --
// branch-free erf-GELU (A&S 7.1.26, abs err ~1.5e-7)
__device__ __forceinline__ float gelu_fast(float h) {
    float z = h * 0.70710678118f;
    float x = fabsf(z);
    float t = __fdividef(1.f, fmaf(0.3275911f, x, 1.f));
    float p = fmaf(1.061405429f, t, -1.453152027f);
    p = fmaf(p, t, 1.421413741f);
    p = fmaf(p, t, -0.284496736f);
    p = fmaf(p, t, 0.254829592f);
    p = p * t;
    float e = __expf(-x * x);
    float er = fmaf(-p, e, 1.f);
    er = copysignf(er, z);
    return 0.5f * h * (1.f + er);
}

// smem: G [64][128] f32 = 32KB ; w2i [64][32] u64 = 16KB ; sp 768B
#define G_OFF  0
#define W_OFF  32768
#define SP_OFF 49152
#define SMEM3  (49152 + 768)

__global__ void __launch_bounds__(256, 3) k_out(const float* __restrict__ gnw,
                                                const float* __restrict__ gnb,
                                                const float* __restrict__ b2,
                                                float* __restrict__ out) {
    extern __shared__ char s[];
    float* G  = (float*)(s + G_OFF);     // [d][px] 64 x 128
    u64* w2i  = (u64*)(s + W_OFF);       // [d][pair] 64 x 32
    float* sp = (float*)(s + SP_OFF);    // a[64], c[64], b2[64]

    const int b  = blockIdx.y;
    const int p0 = blockIdx.x * 128;
    const int t  = threadIdx.x;

    if (t < 64) {
        int g = t >> 3;
        // fused GN-stat finalize (was k_stats): mean/rstd from raw sums
        const float invN = 1.f / (8.f * (float)HW);
        float ssum = g_stats[b * 16 + 2 * g];
        float ssq  = g_stats[b * 16 + 2 * g + 1];
        float mean = ssum * invN;
        float var  = ssq * invN - mean * mean;
        float rstd = rsqrtf(var + 1e-5f);
        float a = rstd * gnw[t];
        sp[t]       = a;
        sp[64 + t]  = gnb[t] - mean * a;
        sp[128 + t] = b2[t];
    }
    // copy prepacked W2 table (coalesced)
    for (int i = t; i < 1024; i += 256)
        *(ulonglong2*)&w2i[i * 2] = *(const ulonglong2*)&g_w2i[i * 2];

    // ---- GN + GELU into G: thread = 4 px x 8 d (fp16 h loads before sync) ----
    const uint32_t* hbu = g_h + (size_t)b * D64 * (HW / 2) + (p0 >> 1);
    const int pxq = (t & 31) * 4;           // pixel base (float index in G)
    const int pxh = (t & 31) * 2;           // half2 index for the same 4 px
    const int dblk = t >> 5;                // 0..7
    uint2 hv2[8];
#pragma unroll
    for (int j = 0; j < 8; j++)
        hv2[j] = __ldcs((const uint2*)&hbu[(size_t)(dblk * 8 + j) * (HW / 2) + pxh]);
    __syncthreads();                        // sp + w2i visible
    {
#pragma unroll
        for (int j = 0; j < 8; j++) {
            int d = dblk * 8 + j;
            float a = sp[d], c = sp[64 + d];
            float2 f01 = __half22float2(*(__half2*)&hv2[j].x);
            float2 f23 = __half22float2(*(__half2*)&hv2[j].y);
            float4 r;
            r.x = gelu_fast(fmaf(f01.x, a, c));
            r.y = gelu_fast(fmaf(f01.y, a, c));
            r.z = gelu_fast(fmaf(f23.x, a, c));
            r.w = gelu_fast(fmaf(f23.y, a, c));
            *(float4*)&G[d * 128 + pxq] = r;
        }
    }
    __syncthreads();

    // ---- GEMM: warp = 128 px x 8 d2 ; thread = 4 px x 4 d2-pairs ----
    const int lane = t & 31;
    const int wrp  = t >> 5;                    // 0..7 -> d2 base 8*wrp
    const int pxb  = lane * 4;
    u64 acc[4][4];                              // [pair][px]
#pragma unroll
    for (int p = 0; p < 4; p++) {
        u64 bp = pack2(sp[128 + 8 * wrp + 2 * p], sp[128 + 8 * wrp + 2 * p + 1]);
#pragma unroll
        for (int x2 = 0; x2 < 4; x2++) acc[p][x2] = bp;
    }

    const float* Gp = G + pxb;
    const u64*   wp = w2i + 4 * wrp;
#pragma unroll 4
    for (int d = 0; d < 64; d++) {
        float4 gv = *(const float4*)Gp;         // 4 px, per-lane LDS.128
        u64 g0 = pack2(gv.x, gv.x);
        u64 g1 = pack2(gv.y, gv.y);
        u64 g2 = pack2(gv.z, gv.z);
        u64 g3 = pack2(gv.w, gv.w);
        ulonglong2 wa = *(const ulonglong2*)(wp);       // pairs 0,1 (uniform)
        ulonglong2 wb = *(const ulonglong2*)(wp + 2);   // pairs 2,3 (uniform)
        acc[0][0] = fma2(wa.x, g0, acc[0][0]);
        acc[0][1] = fma2(wa.x, g1, acc[0][1]);
        acc[0][2] = fma2(wa.x, g2, acc[0][2]);
        acc[0][3] = fma2(wa.x, g3, acc[0][3]);
        acc[1][0] = fma2(wa.y, g0, acc[1][0]);
        acc[1][1] = fma2(wa.y, g1, acc[1][1]);
        acc[1][2] = fma2(wa.y, g2, acc[1][2]);
        acc[1][3] = fma2(wa.y, g3, acc[1][3]);
        acc[2][0] = fma2(wb.x, g0, acc[2][0]);
        acc[2][1] = fma2(wb.x, g1, acc[2][1]);
        acc[2][2] = fma2(wb.x, g2, acc[2][2]);
        acc[2][3] = fma2(wb.x, g3, acc[2][3]);
        acc[3][0] = fma2(wb.y, g0, acc[3][0]);
        acc[3][1] = fma2(wb.y, g1, acc[3][1]);
        acc[3][2] = fma2(wb.y, g2, acc[3][2]);
        acc[3][3] = fma2(wb.y, g3, acc[3][3]);
        Gp += 128; wp += 32;
    }

    // ---- stores: 8 coalesced STG.128 per thread (streaming) ----
    float* ob = out + (size_t)b * D64 * HW + p0 + pxb;
#pragma unroll
    for (int p = 0; p < 4; p++) {
        int d2 = 8 * wrp + 2 * p;
        float2 a0 = unpk(acc[p][0]);
        float2 a1 = unpk(acc[p][1]);
        float2 a2 = unpk(acc[p][2]);
        float2 a3 = unpk(acc[p][3]);
        float4 lo; lo.x = a0.x; lo.y = a1.x; lo.z = a2.x; lo.w = a3.x;
        float4 hi; hi.x = a0.y; hi.y = a1.y; hi.z = a2.y; hi.w = a3.y;
        __stcs((float4*)&ob[(size_t)d2 * HW], lo);
        __stcs((float4*)&ob[(size_t)(d2 + 1) * HW], hi);
    }
}

// ---------------- launch ----------------
extern "C" void kernel_launch(void* const* d_in, const int* in_sizes, int n_in,
                              void* d_out, int out_size) {
    const float* x   = (const float*)d_in[0];
    const float* W1  = (const float*)d_in[1];
    const float* b1  = (const float*)d_in[2];
    const float* gnw = (const float*)d_in[3];
    const float* gnb = (const float*)d_in[4];
    const float* W2  = (const float*)d_in[5];
    const float* b2  = (const float*)d_in[6];
    float* out = (float*)d_out;

    k_init<<<1, 256>>>(W2);

    dim3 g1(Ww / TLX, Hh / TLY, BATCH);   // 6 x 48 x 8
    k_feat<<<g1, 256>>>(x, W1, b1);

    cudaFuncSetAttribute(k_out, cudaFuncAttributeMaxDynamicSharedMemorySize, SMEM3);
    dim3 g3(HW / 128, BATCH);             // 1152 x 8
    k_out<<<g3, 256, SMEM3>>>(gnw, gnb, b2, out);
}

// round 16
// speedup vs baseline: 1.1695x; 1.0159x over previous
#include <cuda_runtime.h>
#include <cuda_fp16.h>
#include <math.h>
#include <stdint.h>

#define Hh 384
#define Ww 384
#define NC 10
#define HW (384*384)
#define BATCH 8
#define D64 64

typedef unsigned long long u64;

// ---- scratch (static device globals: allocation-free) ----
__device__ uint32_t g_h[(size_t)BATCH * D64 * (HW / 2)]; // 151 MB h as half2 pairs
__device__ float g_stats[128];                    // [b][g][{sum,sumsq}]
__device__ float g_mean[64];
__device__ float g_rstd[64];
__device__ u64   g_w2i[2048];                     // packed W2 pairs [d][pair]

// ---------------- packed f32x2 helpers ----------------
__device__ __forceinline__ u64 pack2(float x, float y) {
    u64 r;
    asm("mov.b64 %0, {%1, %2};" : "=l"(r) : "f"(x), "f"(y));
    return r;
}
__device__ __forceinline__ float2 unpk(u64 v) {
    float2 r;
    asm("mov.b64 {%0, %1}, %2;" : "=f"(r.x), "=f"(r.y) : "l"(v));
    return r;
}
__device__ __forceinline__ u64 fma2(u64 a, u64 b, u64 c) {
    u64 d;
    asm("fma.rn.f32x2 %0, %1, %2, %3;" : "=l"(d) : "l"(a), "l"(b), "l"(c));
    return d;
}
__device__ __forceinline__ u64 add2(u64 a, u64 b) {
    u64 d;
    asm("add.rn.f32x2 %0, %1, %2;" : "=l"(d) : "l"(a), "l"(b));
    return d;
}
__device__ __forceinline__ u64 mul2(u64 a, u64 b) {
    u64 d;
    asm("mul.rn.f32x2 %0, %1, %2;" : "=l"(d) : "l"(a), "l"(b));
    return d;
}
#define NEGM 0x8000000080000000ULL
__device__ __forceinline__ u64 sub2(u64 a, u64 b) { return add2(a, b ^ NEGM); }

// ---------------- K_init: zero stats + pack W2 pairs (9 parallel blocks) --
__global__ void k_init(const float* __restrict__ W2) {
    int t = threadIdx.x;
    int blk = blockIdx.x;
    if (blk == 8) {
        if (t < 128) g_stats[t] = 0.f;
        return;
    }
    int i = blk * 256 + t;                 // 0..2047, one entry per thread
    int d = i >> 5, p = i & 31;
    g_w2i[d * 32 + p] = pack2(W2[(2 * p) * 64 + d], W2[(2 * p + 1) * 64 + d]);
}

// ---------------- K1: softmax + neighbor features + W1 (f32x2) ----------
#define TLX 64
#define TLY 8
#define EX 68
#define EY 12
#define PAREA (EX * EY)          // 816

__global__ __launch_bounds__(256, 3) void k_feat(const float* __restrict__ x,
                                                 const float* __restrict__ W1,
                                                 const float* __restrict__ b1) {
    __shared__ float P[NC * PAREA];            // softmax probs, tile + 2px halo
    __shared__ __align__(16) u64 w1p[512];     // {w,w} duplicated
    __shared__ u64 b1p[64];
    __shared__ float sstat[16];

    const int b  = blockIdx.z;
    const int r0 = blockIdx.y * TLY, c0 = blockIdx.x * TLX;
    const int tid = threadIdx.x;

    for (int i = tid; i < 512; i += 256) { float w = W1[i]; w1p[i] = pack2(w, w); }
    if (tid < 64) { float bb = b1[tid]; b1p[tid] = pack2(bb, bb); }
    if (tid < 16) sstat[tid] = 0.f;

    // softmax over C for extended (halo) tile, replicate padding via clamp
    const float* xb = x + (size_t)b * NC * HW;
    for (int i = tid; i < PAREA; i += 256) {
        int er = i / EX, ec2 = i % EX;
        int gr = min(max(r0 + er - 2, 0), Hh - 1);
        int gc = min(max(c0 + ec2 - 2, 0), Ww - 1);
        const float* xp = xb + gr * Ww + gc;
        float v[NC];
        float m = -1e30f;
#pragma unroll
        for (int c = 0; c < NC; c++) { v[c] = xp[(size_t)c * HW]; m = fmaxf(m, v[c]); }
        float ssum = 0.f;
#pragma unroll
        for (int c = 0; c < NC; c++) { v[c] = __expf(v[c] - m); ssum += v[c]; }
        float inv = 1.f / ssum;
#pragma unroll
        for (int c = 0; c < NC; c++) P[c * PAREA + i] = v[c] * inv;
    }
    __syncthreads();

    const int txp = tid & 31;       // pixel-pair index (cols 2*txp, 2*txp+1)
    const int ty  = tid >> 5;       // tile row
    const int rowoff = ty * EX + 2 * txp;

    u64 macc3 = 0, macc5 = 0, pp = 0;
    u64 vacc3 = 0, vacc5 = 0, pbq3 = 0, pbq5 = 0;
    float maj3x = 0.f, maj3y = 0.f, maj5x = 0.f, maj5y = 0.f;
    float en3x = 0.f, en3y = 0.f, en5x = 0.f, en5y = 0.f;

    const u64 K9I  = pack2(1.f / 9.f,  1.f / 9.f);
    const u64 K25I = pack2(1.f / 25.f, 1.f / 25.f);

#pragma unroll 1
    for (int c = 0; c < NC; c++) {
        const float* base = P + c * PAREA + rowoff;
        u64 s5 = 0, q5 = 0, s3 = 0, q3 = 0, pcen = 0;
#pragma unroll
        for (int dr = 0; dr < 5; dr++) {
            const float* rp = base + dr * EX;
            float2 av = *(const float2*)rp;
            float2 bv = *(const float2*)(rp + 2);
            float2 cv = *(const float2*)(rp + 4);
            u64 p0 = pack2(av.x, av.y);
            u64 p1 = pack2(av.y, bv.x);
            u64 p2 = pack2(bv.x, bv.y);
            u64 p3 = pack2(bv.y, cv.x);
            u64 p4 = pack2(cv.x, cv.y);
            u64 s3r = add2(p1, add2(p2, p3));
            u64 s5r = add2(s3r, add2(p0, p4));
            u64 q3r = fma2(p3, p3, fma2(p2, p2, mul2(p1, p1)));
            u64 q5r = fma2(p4, p4, fma2(p0, p0, q3r));
            s5 = add2(s5, s5r);
            q5 = add2(q5, q5r);
            if (dr >= 1 && dr <= 3) {
                s3 = add2(s3, s3r);
                q3 = add2(q3, q3r);
            }
            if (dr == 2) pcen = p2;
        }
        macc3 = fma2(pcen, s3, macc3);
        macc5 = fma2(pcen, s5, macc5);
        pp    = fma2(pcen, pcen, pp);
        float2 s3f = unpk(s3), s5f = unpk(s5);
        maj3x = fmaxf(maj3x, s3f.x); maj3y = fmaxf(maj3y, s3f.y);
        maj5x = fmaxf(maj5x, s5f.x); maj5y = fmaxf(maj5y, s5f.y);
        u64 pb3 = mul2(s3, K9I), pb5 = mul2(s5, K25I);
        vacc3 = fma2(q3, K9I, vacc3);   pbq3 = fma2(pb3, pb3, pbq3);
        vacc5 = fma2(q5, K25I, vacc5);  pbq5 = fma2(pb5, pb5, pbq5);
        float2 pb3f = unpk(pb3), pb5f = unpk(pb5);
        float t0 = fmaxf(pb3f.x, 1e-8f); en3x = fmaf(t0, __logf(t0), en3x);
        float t1 = fmaxf(pb3f.y, 1e-8f); en3y = fmaf(t1, __logf(t1), en3y);
        float t2 = fmaxf(pb5f.x, 1e-8f); en5x = fmaf(t2, __logf(t2), en5x);
        float t3 = fmaxf(pb5f.y, 1e-8f); en5y = fmaf(t3, __logf(t3), en5y);
    }

    const float INV_LOGC = 0.434294481903252f; // 1/ln(10)
    u64 f2[8];
    f2[0] = mul2(sub2(macc3, pp), pack2(1.f / 8.f, 1.f / 8.f));
    f2[1] = mul2(pack2(maj3x, maj3y), K9I);
    f2[2] = pack2(fmaf(en3x, INV_LOGC, 1.f), fmaf(en3y, INV_LOGC, 1.f));
    f2[3] = sub2(vacc3, pbq3);
    f2[4] = mul2(sub2(macc5, pp), pack2(1.f / 24.f, 1.f / 24.f));
    f2[5] = mul2(pack2(maj5x, maj5y), K25I);
    f2[6] = pack2(fmaf(en5x, INV_LOGC, 1.f), fmaf(en5y, INV_LOGC, 1.f));
    f2[7] = sub2(vacc5, pbq5);

    // h = W1 f + b1 -> fp16 store ; stats group-by-group (small live set)
    const int pix = (r0 + ty) * Ww + c0 + 2 * txp;
    uint32_t* hb = g_h + (size_t)b * D64 * (HW / 2) + (pix >> 1);
#pragma unroll 1
    for (int g = 0; g < 8; g++) {
        u64 gs = 0, gq = 0;
#pragma unroll
        for (int j = 0; j < 8; j++) {
            int d = g * 8 + j;
            const ulonglong2* wr = (const ulonglong2*)&w1p[d * 8];
            ulonglong2 w01 = wr[0];
            ulonglong2 w23 = wr[1];
            ulonglong2 w45 = wr[2];
            ulonglong2 w67 = wr[3];
            u64 acc = b1p[d];
            acc = fma2(w01.x, f2[0], acc);
            acc = fma2(w01.y, f2[1], acc);
            acc = fma2(w23.x, f2[2], acc);
            acc = fma2(w23.y, f2[3], acc);
            acc = fma2(w45.x, f2[4], acc);
            acc = fma2(w45.y, f2[5], acc);
            acc = fma2(w67.x, f2[6], acc);
            acc = fma2(w67.y, f2[7], acc);
            float2 av = unpk(acc);
            __half2 hh = __floats2half2_rn(av.x, av.y);
            __stcs((__half2*)&hb[(size_t)d * (HW / 2)], hh);
            gs = add2(gs, acc);
            gq = fma2(acc, acc, gq);
        }
        float2 sa = unpk(gs), qa = unpk(gq);
        float a = sa.x + sa.y, q = qa.x + qa.y;
#pragma unroll
        for (int o = 16; o; o >>= 1) {
            a += __shfl_xor_sync(0xffffffffu, a, o);
            q += __shfl_xor_sync(0xffffffffu, q, o);
        }
        if (txp == 0) { atomicAdd(&sstat[2 * g], a); atomicAdd(&sstat[2 * g + 1], q); }
    }
    __syncthreads();
    if (tid < 16) atomicAdd(&g_stats[b * 16 + tid], sstat[tid]);
}

// ---------------- K2: finalize GN stats ----------------
__global__ void k_stats() {
    int i = threadIdx.x;
    if (i < 64) {
        const float invN = 1.f / (8.f * (float)HW);
        float s  = g_stats[2 * i];
        float ss = g_stats[2 * i + 1];
        float mean = s * invN;
        float var  = ss * invN - mean * mean;
        g_mean[i] = mean;
        g_rstd[i] = rsqrtf(var + 1e-5f);
    }
}

// -------- K3: GN + GELU + W2 (f32x2, X=128px/Y=4pairs per warp, 3 CTAs) --
// branch-free erf-GELU (A&S 7.1.26, abs err ~1.5e-7)
__device__ __forceinline__ float gelu_fast(float h) {
    float z = h * 0.70710678118f;
    float x = fabsf(z);
    float t = __fdividef(1.f, fmaf(0.3275911f, x, 1.f));
    float p = fmaf(1.061405429f, t, -1.453152027f);
    p = fmaf(p, t, 1.421413741f);
    p = fmaf(p, t, -0.284496736f);
    p = fmaf(p, t, 0.254829592f);
    p = p * t;
    float e = __expf(-x * x);
    float er = fmaf(-p, e, 1.f);
    er = copysignf(er, z);
    return 0.5f * h * (1.f + er);
}

// smem: G [64][128] f32 = 32KB ; w2i [64][32] u64 = 16KB ; sp 768B
#define G_OFF  0
#define W_OFF  32768
#define SP_OFF 49152
#define SMEM3  (49152 + 768)

__global__ void __launch_bounds__(256, 3) k_out(const float* __restrict__ gnw,
                                                const float* __restrict__ gnb,
                                                const float* __restrict__ b2,
                                                float* __restrict__ out) {
    extern __shared__ char s[];
    float* G  = (float*)(s + G_OFF);     // [d][px] 64 x 128
    u64* w2i  = (u64*)(s + W_OFF);       // [d][pair] 64 x 32
    float* sp = (float*)(s + SP_OFF);    // a[64], c[64], b2[64]

    const int b  = blockIdx.y;
    const int p0 = blockIdx.x * 128;
    const int t  = threadIdx.x;

    if (t < 64) {
        int g = t >> 3;
        float a = g_rstd[b * 8 + g] * gnw[t];
        sp[t]       = a;
        sp[64 + t]  = gnb[t] - g_mean[b * 8 + g] * a;
        sp[128 + t] = b2[t];
    }
    // copy prepacked W2 table (coalesced)
    for (int i = t; i < 1024; i += 256)
        *(ulonglong2*)&w2i[i * 2] = *(const ulonglong2*)&g_w2i[i * 2];

    // ---- GN + GELU into G: thread = 4 px x 8 d (fp16 h loads before sync) ----
    const uint32_t* hbu = g_h + (size_t)b * D64 * (HW / 2) + (p0 >> 1);
    const int pxq = (t & 31) * 4;           // pixel base (float index in G)
    const int pxh = (t & 31) * 2;           // half2 index for the same 4 px
    const int dblk = t >> 5;                // 0..7
    uint2 hv2[8];
#pragma unroll
    for (int j = 0; j < 8; j++)
        hv2[j] = __ldcs((const uint2*)&hbu[(size_t)(dblk * 8 + j) * (HW / 2) + pxh]);
    __syncthreads();                        // sp + w2i visible
    {
#pragma unroll
        for (int j = 0; j < 8; j++) {
            int d = dblk * 8 + j;
            float a = sp[d], c = sp[64 + d];
            float2 f01 = __half22float2(*(__half2*)&hv2[j].x);
            float2 f23 = __half22float2(*(__half2*)&hv2[j].y);
            float4 r;
            r.x = gelu_fast(fmaf(f01.x, a, c));
            r.y = gelu_fast(fmaf(f01.y, a, c));
            r.z = gelu_fast(fmaf(f23.x, a, c));
            r.w = gelu_fast(fmaf(f23.y, a, c));
            *(float4*)&G[d * 128 + pxq] = r;
        }
    }
    __syncthreads();

    // ---- GEMM: warp = 128 px x 8 d2 ; thread = 4 px x 4 d2-pairs ----
    const int lane = t & 31;
    const int wrp  = t >> 5;                    // 0..7 -> d2 base 8*wrp
    const int pxb  = lane * 4;
    u64 acc[4][4];                              // [pair][px]
#pragma unroll
    for (int p = 0; p < 4; p++) {
        u64 bp = pack2(sp[128 + 8 * wrp + 2 * p], sp[128 + 8 * wrp + 2 * p + 1]);
#pragma unroll
        for (int x2 = 0; x2 < 4; x2++) acc[p][x2] = bp;
    }

    const float* Gp = G + pxb;
    const u64*   wp = w2i + 4 * wrp;
#pragma unroll 4
    for (int d = 0; d < 64; d++) {
        float4 gv = *(const float4*)Gp;         // 4 px, per-lane LDS.128
        u64 g0 = pack2(gv.x, gv.x);
        u64 g1 = pack2(gv.y, gv.y);
        u64 g2 = pack2(gv.z, gv.z);
        u64 g3 = pack2(gv.w, gv.w);
        ulonglong2 wa = *(const ulonglong2*)(wp);       // pairs 0,1 (uniform)
        ulonglong2 wb = *(const ulonglong2*)(wp + 2);   // pairs 2,3 (uniform)
        acc[0][0] = fma2(wa.x, g0, acc[0][0]);
        acc[0][1] = fma2(wa.x, g1, acc[0][1]);
        acc[0][2] = fma2(wa.x, g2, acc[0][2]);
        acc[0][3] = fma2(wa.x, g3, acc[0][3]);
        acc[1][0] = fma2(wa.y, g0, acc[1][0]);
        acc[1][1] = fma2(wa.y, g1, acc[1][1]);
        acc[1][2] = fma2(wa.y, g2, acc[1][2]);
        acc[1][3] = fma2(wa.y, g3, acc[1][3]);
        acc[2][0] = fma2(wb.x, g0, acc[2][0]);
        acc[2][1] = fma2(wb.x, g1, acc[2][1]);
        acc[2][2] = fma2(wb.x, g2, acc[2][2]);
        acc[2][3] = fma2(wb.x, g3, acc[2][3]);
        acc[3][0] = fma2(wb.y, g0, acc[3][0]);
        acc[3][1] = fma2(wb.y, g1, acc[3][1]);
        acc[3][2] = fma2(wb.y, g2, acc[3][2]);
        acc[3][3] = fma2(wb.y, g3, acc[3][3]);
        Gp += 128; wp += 32;
    }

    // ---- stores: 8 coalesced STG.128 per thread (streaming) ----
    float* ob = out + (size_t)b * D64 * HW + p0 + pxb;
#pragma unroll
    for (int p = 0; p < 4; p++) {
        int d2 = 8 * wrp + 2 * p;
        float2 a0 = unpk(acc[p][0]);
        float2 a1 = unpk(acc[p][1]);
        float2 a2 = unpk(acc[p][2]);
        float2 a3 = unpk(acc[p][3]);
        float4 lo; lo.x = a0.x; lo.y = a1.x; lo.z = a2.x; lo.w = a3.x;
        float4 hi; hi.x = a0.y; hi.y = a1.y; hi.z = a2.y; hi.w = a3.y;
        __stcs((float4*)&ob[(size_t)d2 * HW], lo);
        __stcs((float4*)&ob[(size_t)(d2 + 1) * HW], hi);
    }
}

// ---------------- launch ----------------
extern "C" void kernel_launch(void* const* d_in, const int* in_sizes, int n_in,
                              void* d_out, int out_size) {
    const float* x   = (const float*)d_in[0];
    const float* W1  = (const float*)d_in[1];
    const float* b1  = (const float*)d_in[2];
    const float* gnw = (const float*)d_in[3];
    const float* gnb = (const float*)d_in[4];
    const float* W2  = (const float*)d_in[5];
    const float* b2  = (const float*)d_in[6];
    float* out = (float*)d_out;

    k_init<<<9, 256>>>(W2);

    dim3 g1(Ww / TLX, Hh / TLY, BATCH);   // 6 x 48 x 8
    k_feat<<<g1, 256>>>(x, W1, b1);

    k_stats<<<1, 64>>>();

    cudaFuncSetAttribute(k_out, cudaFuncAttributeMaxDynamicSharedMemorySize, SMEM3);
    dim3 g3(HW / 128, BATCH);             // 1152 x 8
    k_out<<<g3, 256, SMEM3>>>(gnw, gnb, b2, out);
}